// round 11
// baseline (speedup 1.0000x reference)
#include <cuda_runtime.h>
#include <cuda_bf16.h>
#include <math.h>

#define Bsz   8
#define Cch   256
#define Lseq  1024
#define Mtok  8192      // Bsz*Lseq
#define DIdim 512
#define DSdim 16
#define NLAYER 4

// ---------------- scratch (device globals: no allocations allowed) ----------
__device__ __align__(128) float g_xs  [Mtok*Cch];            // residual stream (b,l,c) fp32
__device__ __align__(128) __nv_bfloat16 g_xn_bf[Mtok*Cch];   // layernorm out (GEMM A)
__device__ __align__(128) __nv_bfloat16 g_xz_bf[Mtok*2*DIdim]; // in_proj out bf16: xin | z
__device__ __align__(128) __nv_bfloat16 g_xc_bf[Mtok*DIdim]; // conv+silu out bf16
__device__ __align__(128) float g_proj[Mtok*48];             // x_proj out (dtr|B|C) fp32
__device__ __align__(128) __nv_bfloat16 g_y_bf[Mtok*DIdim];  // gated scan out bf16 (GEMM A)
__device__ __align__(128) float g_g0  [Bsz*Cch];             // SE pooled
__device__ __align__(128) float g_gate[Bsz*Cch];             // SE sigmoid gate
__device__ __align__(128) float g_ybn [Bsz*Cch*Lseq];        // pre-BN output (b,c,l)
__device__ __align__(128) float g_stats[2*Cch];              // BN raw sums: [c]=S, [256+c]=S2
// bf16 weight copies
__device__ __align__(128) __nv_bfloat16 g_win_bf [NLAYER*2*DIdim*Cch];
__device__ __align__(128) __nv_bfloat16 g_wx_bf  [NLAYER*48*DIdim];
__device__ __align__(128) __nv_bfloat16 g_wout_bf[NLAYER*Cch*DIdim];

// ---------------- helpers ----------------------------------------------------
__device__ __forceinline__ float siluf(float v) { return v / (1.f + __expf(-v)); }

__device__ __forceinline__ void mma_bf16(float* d, const unsigned* a, const unsigned* b) {
    asm volatile(
        "mma.sync.aligned.m16n8k16.row.col.f32.bf16.bf16.f32 "
        "{%0,%1,%2,%3}, {%4,%5,%6,%7}, {%8,%9}, {%0,%1,%2,%3};"
        : "+f"(d[0]), "+f"(d[1]), "+f"(d[2]), "+f"(d[3])
        : "r"(a[0]), "r"(a[1]), "r"(a[2]), "r"(a[3]), "r"(b[0]), "r"(b[1]));
}
__device__ __forceinline__ void ldsm4(unsigned& r0, unsigned& r1, unsigned& r2,
                                      unsigned& r3, unsigned addr) {
    asm volatile("ldmatrix.sync.aligned.m8n8.x4.shared.b16 {%0,%1,%2,%3}, [%4];"
                 : "=r"(r0), "=r"(r1), "=r"(r2), "=r"(r3) : "r"(addr));
}
__device__ __forceinline__ unsigned smaddr(const void* p) {
    return (unsigned)__cvta_generic_to_shared(p);
}
__device__ __forceinline__ void cpasync16(unsigned dst, const void* src, int srcbytes) {
    asm volatile("cp.async.cg.shared.global [%0], [%1], 16, %2;"
                 :: "r"(dst), "l"(src), "r"(srcbytes));
}

// ---------------- weight fp32 -> bf16 ---------------------------------------
__global__ void k_cvtw(const float* __restrict__ win, const float* __restrict__ wx,
                       const float* __restrict__ wo) {
    int i = blockIdx.x * 256 + threadIdx.x;
    if (i < NLAYER*2*DIdim*Cch) g_win_bf[i]  = __float2bfloat16(win[i]);
    if (i < NLAYER*48*DIdim)    g_wx_bf[i]   = __float2bfloat16(wx[i]);
    if (i < NLAYER*Cch*DIdim)   g_wout_bf[i] = __float2bfloat16(wo[i]);
}

// ---------------- input transpose (b,c,l) -> (b,l,c) -------------------------
__global__ void k_transpose_in(const float* __restrict__ x) {
    __shared__ float tile[32][33];
    int b = blockIdx.z, c0 = blockIdx.y * 32, l0 = blockIdx.x * 32;
    int tx = threadIdx.x, ty = threadIdx.y;
    #pragma unroll
    for (int i = ty; i < 32; i += 8)
        tile[i][tx] = x[(size_t)(b*Cch + c0 + i)*Lseq + l0 + tx];
    __syncthreads();
    #pragma unroll
    for (int i = ty; i < 32; i += 8)
        g_xs[(size_t)(b*Lseq + l0 + i)*Cch + c0 + tx] = tile[tx][i];
}

// ---------------- layernorm: warp per token, 8 tokens/block ------------------
__global__ void k_ln(const float* __restrict__ w, const float* __restrict__ bias) {
    int warp = threadIdx.x >> 5, lane = threadIdx.x & 31;
    int m = blockIdx.x * 8 + warp;
    const float* row = g_xs + (size_t)m*Cch;
    float v[8], s = 0.f, s2 = 0.f;
    #pragma unroll
    for (int j = 0; j < 8; j++) {
        v[j] = row[lane + 32*j];
        s += v[j]; s2 += v[j]*v[j];
    }
    #pragma unroll
    for (int o = 16; o > 0; o >>= 1) {
        s  += __shfl_xor_sync(0xffffffffu, s, o);
        s2 += __shfl_xor_sync(0xffffffffu, s2, o);
    }
    float mu = s * (1.f/256.f);
    float r  = rsqrtf(s2 * (1.f/256.f) - mu*mu + 1e-5f);
    #pragma unroll
    for (int j = 0; j < 8; j++) {
        int c = lane + 32*j;
        g_xn_bf[(size_t)m*Cch + c] = __float2bfloat16((v[j] - mu)*r*w[c] + bias[c]);
    }
}

// ---------------- bf16 tensor GEMM: C[M,N] (+)= A[M,K] @ W[N,K]^T ------------
// BM=128, BN=64, BK=32, 256 threads = 8 warps (4 M x 2 N), warp tile 32x32.
// 3-stage cp.async, one barrier per chunk; ldmatrix.x4; GP=20 pad; occ 3.
#define GP 20
#define STG 3
#define TILEA (128*GP)
#define TILEB (64*GP)
#define GEMM_SMEM (STG*(TILEA+TILEB)*4)
template<bool ACC, bool BF16OUT>
__launch_bounds__(256, 3)
__global__ void k_gemm_bf(const __nv_bfloat16* __restrict__ A,
                          const __nv_bfloat16* __restrict__ W,
                          void* __restrict__ CoutV, int N, int Kd)
{
    extern __shared__ __align__(16) unsigned smbuf[];
    unsigned* As = smbuf;                 // STG A tiles
    unsigned* Bs = smbuf + STG*TILEA;     // STG B tiles
    const int m0 = blockIdx.y * 128, n0 = blockIdx.x * 64;
    const int tid  = threadIdx.x;
    const int warp = tid >> 5, lane = tid & 31;
    const int wm = (warp & 3) * 32;
    const int wn = (warp >> 2) * 32;
    const int grp = lane >> 2, tig = lane & 3;
    const int l15 = lane & 15, lhi = (lane >> 4) * 4;

    float acc[2][4][4];
    #pragma unroll
    for (int mt = 0; mt < 2; mt++)
        #pragma unroll
        for (int nt = 0; nt < 4; nt++)
            #pragma unroll
            for (int q = 0; q < 4; q++) acc[mt][nt][q] = 0.f;

    const int NC = Kd >> 5;

    auto preload = [&](int c) {
        unsigned* Ab = As + (c % STG) * TILEA;
        unsigned* Bb = Bs + (c % STG) * TILEB;
        #pragma unroll
        for (int i = 0; i < 2; i++) {
            int id = tid + i*256;
            int rr = id >> 2, qq = id & 3;
            cpasync16(smaddr(Ab + rr*GP + qq*4),
                      A + (size_t)(m0 + rr)*Kd + c*32 + qq*8, 16);
        }
        {
            int rr = tid >> 2, qq = tid & 3;      // 64 rows x 4 quads
            int valid = (n0 + rr < N);
            cpasync16(smaddr(Bb + rr*GP + qq*4),
                      W + (size_t)(valid ? (n0 + rr) : 0)*Kd + c*32 + qq*8,
                      valid ? 16 : 0);
        }
        asm volatile("cp.async.commit_group;");
    };

    preload(0);
    if (NC > 1) preload(1);
    for (int c = 0; c < NC; c++) {
        if (c + 1 < NC) { asm volatile("cp.async.wait_group 1;"); }
        else            { asm volatile("cp.async.wait_group 0;"); }
        __syncthreads();
        if (c + 2 < NC) preload(c + 2);
        const unsigned* Ab = As + (c % STG) * TILEA;
        const unsigned* Bb = Bs + (c % STG) * TILEB;
        #pragma unroll
        for (int ks = 0; ks < 2; ks++) {
            int kc = ks * 8;
            unsigned af[2][4], bf[4][2];
            #pragma unroll
            for (int mt = 0; mt < 2; mt++)
                ldsm4(af[mt][0], af[mt][1], af[mt][2], af[mt][3],
                      smaddr(Ab + (wm + mt*16 + l15)*GP + kc + lhi));
            #pragma unroll
            for (int pr = 0; pr < 2; pr++)
                ldsm4(bf[2*pr][0], bf[2*pr+1][0], bf[2*pr][1], bf[2*pr+1][1],
                      smaddr(Bb + (wn + pr*16 + l15)*GP + kc + lhi));
            #pragma unroll
            for (int mt = 0; mt < 2; mt++)
                #pragma unroll
                for (int nt = 0; nt < 4; nt++)
                    mma_bf16(acc[mt][nt], af[mt], bf[nt]);
        }
    }

    // epilogue: c0,c1 -> (grp, 2tig); c2,c3 -> (grp+8, 2tig)
    #pragma unroll
    for (int mt = 0; mt < 2; mt++) {
        #pragma unroll
        for (int nt = 0; nt < 4; nt++) {
            int m = m0 + wm + mt*16 + grp;
            int n = n0 + wn + nt*8 + 2*tig;
            if (n < N) {
                if (BF16OUT) {
                    __nv_bfloat16* Cb = (__nv_bfloat16*)CoutV;
                    *(__nv_bfloat162*)(Cb + (size_t)m*N + n) =
                        __floats2bfloat162_rn(acc[mt][nt][0], acc[mt][nt][1]);
                    *(__nv_bfloat162*)(Cb + (size_t)(m+8)*N + n) =
                        __floats2bfloat162_rn(acc[mt][nt][2], acc[mt][nt][3]);
                } else {
                    float* Cf = (float*)CoutV;
                    float2* p0 = (float2*)(Cf + (size_t)m*N + n);
                    float2* p1 = (float2*)(Cf + (size_t)(m+8)*N + n);
                    if (ACC) {
                        float2 v0 = *p0, v1 = *p1;
                        v0.x += acc[mt][nt][0]; v0.y += acc[mt][nt][1];
                        v1.x += acc[mt][nt][2]; v1.y += acc[mt][nt][3];
                        *p0 = v0; *p1 = v1;
                    } else {
                        *p0 = make_float2(acc[mt][nt][0], acc[mt][nt][1]);
                        *p1 = make_float2(acc[mt][nt][2], acc[mt][nt][3]);
                    }
                }
            }
        }
    }
}

// ---------------- depthwise causal conv (K=4) + silu, 4 tok x 2 ch / thread --
__global__ void k_conv(const float* __restrict__ w, const float* __restrict__ bias) {
    int idx = blockIdx.x * 256 + threadIdx.x;      // over Mtok*DIdim/8
    int d = (idx & 255) * 2;                        // even channel of the pair
    int mg = idx >> 8;                              // token group of 4
    int m0 = mg * 4;
    int l0 = m0 & (Lseq - 1);
    float lo[7], hi[7];
    #pragma unroll
    for (int k = 0; k < 7; k++) {
        int l = l0 - 3 + k;
        if (l >= 0) {
            __nv_bfloat162 v =
                *(const __nv_bfloat162*)&g_xz_bf[(size_t)(m0 - 3 + k)*(2*DIdim) + d];
            lo[k] = __bfloat162float(v.x); hi[k] = __bfloat162float(v.y);
        } else { lo[k] = 0.f; hi[k] = 0.f; }
    }
    float wa0 = w[d*4+0], wa1 = w[d*4+1], wa2 = w[d*4+2], wa3 = w[d*4+3];
    float wb0 = w[d*4+4], wb1 = w[d*4+5], wb2 = w[d*4+6], wb3 = w[d*4+7];
    float ba = bias[d], bb = bias[d+1];
    #pragma unroll
    for (int j = 0; j < 4; j++) {
        float s0 = ba + wa0*lo[j] + wa1*lo[j+1] + wa2*lo[j+2] + wa3*lo[j+3];
        float s1 = bb + wb0*hi[j] + wb1*hi[j+1] + wb2*hi[j+2] + wb3*hi[j+3];
        *(__nv_bfloat162*)&g_xc_bf[(size_t)(m0 + j)*DIdim + d] =
            __floats2bfloat162_rn(siluf(s0), siluf(s1));
    }
}

// ---------------- selective scan (dt fused, shuffle reduction, gated) --------
// block: 256 thr = 16 channels (dg) x 16 states (n); half-warp owns a channel.
// Serial loop: h recurrence per lane; p=h*C reduced over n via 4 shfl_xor
// (width 16) INSIDE the loop (pipelines behind the h FMA chain); lane n==0
// adds D-term, applies silu(z) gate, stores bf16. No s_p, 3 barriers/chunk.
__launch_bounds__(256)
__global__ void k_scan3(const float* __restrict__ alog, const float* __restrict__ Dp,
                        const float* __restrict__ dw, const float* __restrict__ db) {
    __shared__ __align__(16) float s_dt[32][16], s_x[32][16], s_B[32][16], s_C[32][16];
    __shared__ __align__(16) float s_z[32][16];
    __shared__ __align__(16) float s_P[32][16];
    __shared__ float s_dw[16][17];
    __shared__ float s_db[16];
    int b  = blockIdx.x >> 5;
    int d0 = (blockIdx.x & 31) << 4;
    int tid = threadIdx.x;
    int n  = tid & 15, dg = tid >> 4;
    int d  = d0 + dg;
    float Ad = -__expf(alog[d*DSdim + n]);
    float Dv = Dp[d];
    if (tid < 16) s_db[tid] = db[d0 + tid];
    s_dw[tid >> 4][tid & 15] = dw[(d0 + (tid >> 4))*16 + (tid & 15)];
    float h = 0.f;
    float rP[2], rx[2], rB[2], rC[2], rZ[2];

    auto ldc = [&](int l0) {
        #pragma unroll
        for (int it = 0; it < 2; it++) {
            int i = tid + it*256;
            int l = i >> 4, j = i & 15;
            size_t t = (size_t)(b*Lseq + l0 + l);
            rP[it] = g_proj[t*48 + j];
            rx[it] = __bfloat162float(g_xc_bf[t*DIdim + d0 + j]);
            rB[it] = g_proj[t*48 + 16 + j];
            rC[it] = g_proj[t*48 + 32 + j];
            rZ[it] = __bfloat162float(g_xz_bf[t*(2*DIdim) + DIdim + d0 + j]);
        }
    };
    auto stc = [&]() {
        #pragma unroll
        for (int it = 0; it < 2; it++) {
            int i = tid + it*256;
            int l = i >> 4, j = i & 15;
            s_P[l][j] = rP[it]; s_x[l][j] = rx[it];
            s_B[l][j] = rB[it]; s_C[l][j] = rC[it];
            s_z[l][j] = rZ[it];
        }
    };
    auto dtcalc = [&]() {
        #pragma unroll
        for (int it = 0; it < 2; it++) {
            int i = tid + it*256;
            int l = i >> 4, j = i & 15;
            float s = s_db[j];
            #pragma unroll
            for (int r = 0; r < 16; r++) s += s_P[l][r] * s_dw[j][r];
            s_dt[l][j] = (s > 15.f) ? s : __logf(1.f + __expf(s));
        }
    };

    ldc(0); stc(); __syncthreads(); dtcalc(); __syncthreads();
    for (int ch = 0; ch < 32; ch++) {
        int l0 = ch * 32;
        if (ch < 31) ldc(l0 + 32);      // LDGs in flight during serial phase
        #pragma unroll 8
        for (int l = 0; l < 32; l++) {
            float dtv = s_dt[l][dg];
            float xv  = s_x[l][dg];
            float w = __expf(dtv * Ad);
            h = h * w + (dtv * xv) * s_B[l][n];
            float pp = h * s_C[l][n];
            pp += __shfl_xor_sync(0xffffffffu, pp, 8, 16);
            pp += __shfl_xor_sync(0xffffffffu, pp, 4, 16);
            pp += __shfl_xor_sync(0xffffffffu, pp, 2, 16);
            pp += __shfl_xor_sync(0xffffffffu, pp, 1, 16);
            if (n == 0) {
                float yv = pp + xv * Dv;
                float z = s_z[l][dg];
                yv *= z / (1.f + __expf(-z));
                g_y_bf[(size_t)(b*Lseq + l0 + l)*DIdim + d] = __float2bfloat16(yv);
            }
        }
        __syncthreads();
        if (ch < 31) { stc(); __syncthreads(); dtcalc(); __syncthreads(); }
    }
}

// ---------------- SE pool (direct, also zeros BN sums) -----------------------
__global__ void k_pool2() {            // grid Bsz, block 1024
    int b = blockIdx.x, t = threadIdx.x;
    int c = t & 255, q = t >> 8;
    float s = 0.f;
    for (int l = q*256; l < q*256 + 256; l++)
        s += g_xs[(size_t)(b*Lseq + l)*Cch + c];
    __shared__ float sm[4][256];
    sm[q][c] = s;
    __syncthreads();
    if (q == 0)
        g_g0[b*Cch + c] = (sm[0][c] + sm[1][c] + sm[2][c] + sm[3][c]) * (1.f/1024.f);
    if (b == 0 && t < 512) g_stats[t] = 0.f;
}
__global__ void k_se(const float* __restrict__ w1, const float* __restrict__ b1,
                     const float* __restrict__ w2, const float* __restrict__ b2) {
    __shared__ float sg[Bsz*Cch];
    __shared__ float sh[Bsz*64];
    int t = threadIdx.x;
    for (int i = t; i < Bsz*Cch; i += 256) sg[i] = g_g0[i];
    __syncthreads();
    for (int i = t; i < Bsz*64; i += 256) {
        int b = i >> 6, j = i & 63;
        float s = b1[j];
        const float* wr = w1 + j*256;
        const float* gr = sg + b*256;
        #pragma unroll 8
        for (int c = 0; c < 256; c++) s += gr[c] * wr[c];
        sh[i] = fmaxf(s, 0.f);
    }
    __syncthreads();
    for (int i = t; i < Bsz*Cch; i += 256) {
        int b = i >> 8, c = i & 255;
        float s = b2[c];
        const float* wr = w2 + c*64;
        const float* hr = sh + b*64;
        #pragma unroll 8
        for (int j = 0; j < 64; j++) s += hr[j] * wr[j];
        g_gate[i] = 1.f / (1.f + __expf(-s));
    }
}

// ---------------- y = xo*g + residual (b,c,l) + fused BN partial sums --------
__global__ void k_ybn(const float* __restrict__ x) {
    __shared__ float tile[32][33];
    int b = blockIdx.z, c0 = blockIdx.y * 32, l0 = blockIdx.x * 32;
    int tx = threadIdx.x, ty = threadIdx.y;
    #pragma unroll
    for (int i = ty; i < 32; i += 8)
        tile[i][tx] = g_xs[(size_t)(b*Lseq + l0 + i)*Cch + c0 + tx];   // tile[l][c]
    __syncthreads();
    #pragma unroll
    for (int i = ty; i < 32; i += 8) {
        int c = c0 + i;
        size_t o = (size_t)(b*Cch + c)*Lseq + l0 + tx;
        float v = tile[tx][i] * g_gate[b*Cch + c] + x[o];
        g_ybn[o] = v;
        float s = v, s2 = v*v;
        #pragma unroll
        for (int w = 16; w > 0; w >>= 1) {
            s  += __shfl_xor_sync(0xffffffffu, s, w);
            s2 += __shfl_xor_sync(0xffffffffu, s2, w);
        }
        if (tx == 0) {
            atomicAdd(&g_stats[c], s);
            atomicAdd(&g_stats[Cch + c], s2);
        }
    }
}

// ---------------- batchnorm apply (stats from raw sums) ----------------------
__global__ void k_bnapply(float* __restrict__ out, const float* __restrict__ bw,
                          const float* __restrict__ bb) {
    int idx = blockIdx.x * 256 + threadIdx.x;   // Bsz*Cch*Lseq
    int c = (idx >> 10) & 255;
    float mu  = g_stats[c] * (1.f/8192.f);
    float var = g_stats[Cch + c] * (1.f/8192.f) - mu*mu;
    out[idx] = (g_ybn[idx] - mu) * rsqrtf(var + 1e-5f) * bw[c] + bb[c];
}

// ---------------- host driver ------------------------------------------------
extern "C" void kernel_launch(void* const* d_in, const int* in_sizes, int n_in,
                              void* d_out, int out_size)
{
    const float* x         = (const float*)d_in[0];
    const float* ln_w      = (const float*)d_in[1];
    const float* ln_b      = (const float*)d_in[2];
    const float* in_proj_w = (const float*)d_in[3];
    const float* conv_w    = (const float*)d_in[4];
    const float* conv_b    = (const float*)d_in[5];
    const float* x_proj_w  = (const float*)d_in[6];
    const float* dt_proj_w = (const float*)d_in[7];
    const float* dt_proj_b = (const float*)d_in[8];
    const float* A_log     = (const float*)d_in[9];
    const float* Dp        = (const float*)d_in[10];
    const float* out_proj_w= (const float*)d_in[11];
    const float* se_w1     = (const float*)d_in[12];
    const float* se_b1     = (const float*)d_in[13];
    const float* se_w2     = (const float*)d_in[14];
    const float* se_b2     = (const float*)d_in[15];
    const float* bn_w      = (const float*)d_in[16];
    const float* bn_b      = (const float*)d_in[17];
    float* out = (float*)d_out;

    void *p;
    cudaGetSymbolAddress(&p, g_xn_bf);   __nv_bfloat16* pxn  = (__nv_bfloat16*)p;
    cudaGetSymbolAddress(&p, g_xz_bf);   __nv_bfloat16* pxzb = (__nv_bfloat16*)p;
    cudaGetSymbolAddress(&p, g_xc_bf);   __nv_bfloat16* pxcb = (__nv_bfloat16*)p;
    cudaGetSymbolAddress(&p, g_proj);    float* pproj = (float*)p;
    cudaGetSymbolAddress(&p, g_y_bf);    __nv_bfloat16* pyb  = (__nv_bfloat16*)p;
    cudaGetSymbolAddress(&p, g_xs);      float* pxs  = (float*)p;
    cudaGetSymbolAddress(&p, g_win_bf);  __nv_bfloat16* pwin = (__nv_bfloat16*)p;
    cudaGetSymbolAddress(&p, g_wx_bf);   __nv_bfloat16* pwx  = (__nv_bfloat16*)p;
    cudaGetSymbolAddress(&p, g_wout_bf); __nv_bfloat16* pwo  = (__nv_bfloat16*)p;

    cudaFuncSetAttribute(k_gemm_bf<false, true>,
                         cudaFuncAttributeMaxDynamicSharedMemorySize, GEMM_SMEM);
    cudaFuncSetAttribute(k_gemm_bf<false, false>,
                         cudaFuncAttributeMaxDynamicSharedMemorySize, GEMM_SMEM);
    cudaFuncSetAttribute(k_gemm_bf<true, false>,
                         cudaFuncAttributeMaxDynamicSharedMemorySize, GEMM_SMEM);

    k_cvtw<<<(NLAYER*2*DIdim*Cch + 255)/256, 256>>>(in_proj_w, x_proj_w, out_proj_w);
    dim3 tb(32, 8);
    k_transpose_in<<<dim3(32, 8, Bsz), tb>>>(x);

    for (int i = 0; i < NLAYER; i++) {
        k_ln<<<Mtok/8, 256>>>(ln_w + i*Cch, ln_b + i*Cch);
        k_gemm_bf<false, true><<<dim3(16, 64), 256, GEMM_SMEM>>>(
            pxn, pwin + (size_t)i*2*DIdim*Cch, pxzb, 2*DIdim, Cch);
        k_conv<<<Mtok*DIdim/2048, 256>>>(conv_w + i*DIdim*4, conv_b + i*DIdim);
        k_gemm_bf<false, false><<<dim3(1, 64), 256, GEMM_SMEM>>>(
            pxcb, pwx + (size_t)i*48*DIdim, pproj, 48, DIdim);
        k_scan3<<<256, 256>>>(A_log + i*DIdim*DSdim, Dp + i*DIdim,
                              dt_proj_w + i*DIdim*16, dt_proj_b + i*DIdim);
        k_gemm_bf<true, false><<<dim3(4, 64), 256, GEMM_SMEM>>>(
            pyb, pwo + (size_t)i*Cch*DIdim, pxs, Cch, DIdim);
    }

    k_pool2<<<Bsz, 1024>>>();
    k_se<<<1, 256>>>(se_w1, se_b1, se_w2, se_b2);
    k_ybn<<<dim3(32, 8, Bsz), tb>>>(x);
    k_bnapply<<<Bsz*Cch*Lseq/256, 256>>>(out, bn_w, bn_b);

    (void)in_sizes; (void)n_in; (void)out_size;
}

// round 12
// speedup vs baseline: 1.7064x; 1.7064x over previous
#include <cuda_runtime.h>
#include <cuda_bf16.h>
#include <math.h>

#define Bsz   8
#define Cch   256
#define Lseq  1024
#define Mtok  8192      // Bsz*Lseq
#define DIdim 512
#define DSdim 16
#define NLAYER 4

// ---------------- scratch (device globals: no allocations allowed) ----------
__device__ __align__(128) float g_xs  [Mtok*Cch];            // residual stream (b,l,c) fp32
__device__ __align__(128) __nv_bfloat16 g_xn_bf[Mtok*Cch];   // layernorm out (GEMM A)
__device__ __align__(128) __nv_bfloat16 g_xz_bf[Mtok*2*DIdim]; // in_proj out bf16: xin | z
__device__ __align__(128) __nv_bfloat16 g_xc_bf[Mtok*DIdim]; // conv+silu out bf16
__device__ __align__(128) float g_proj[Mtok*48];             // x_proj out (dtr|B|C) fp32
__device__ __align__(128) __nv_bfloat16 g_y_bf[Mtok*DIdim];  // gated scan out bf16 (GEMM A)
__device__ __align__(128) float g_g0  [Bsz*Cch];             // SE pooled
__device__ __align__(128) float g_gate[Bsz*Cch];             // SE sigmoid gate
__device__ __align__(128) float g_ybn [Bsz*Cch*Lseq];        // pre-BN output (b,c,l)
__device__ __align__(128) float g_stats[2*Cch];              // BN raw sums: [c]=S, [256+c]=S2
// bf16 weight copies
__device__ __align__(128) __nv_bfloat16 g_win_bf [NLAYER*2*DIdim*Cch];
__device__ __align__(128) __nv_bfloat16 g_wx_bf  [NLAYER*48*DIdim];
__device__ __align__(128) __nv_bfloat16 g_wout_bf[NLAYER*Cch*DIdim];

// ---------------- helpers ----------------------------------------------------
__device__ __forceinline__ float siluf(float v) { return v / (1.f + __expf(-v)); }

__device__ __forceinline__ void mma_bf16(float* d, const unsigned* a, const unsigned* b) {
    asm volatile(
        "mma.sync.aligned.m16n8k16.row.col.f32.bf16.bf16.f32 "
        "{%0,%1,%2,%3}, {%4,%5,%6,%7}, {%8,%9}, {%0,%1,%2,%3};"
        : "+f"(d[0]), "+f"(d[1]), "+f"(d[2]), "+f"(d[3])
        : "r"(a[0]), "r"(a[1]), "r"(a[2]), "r"(a[3]), "r"(b[0]), "r"(b[1]));
}
__device__ __forceinline__ void ldsm4(unsigned& r0, unsigned& r1, unsigned& r2,
                                      unsigned& r3, unsigned addr) {
    asm volatile("ldmatrix.sync.aligned.m8n8.x4.shared.b16 {%0,%1,%2,%3}, [%4];"
                 : "=r"(r0), "=r"(r1), "=r"(r2), "=r"(r3) : "r"(addr));
}
__device__ __forceinline__ unsigned smaddr(const void* p) {
    return (unsigned)__cvta_generic_to_shared(p);
}
__device__ __forceinline__ void cpasync16(unsigned dst, const void* src, int srcbytes) {
    asm volatile("cp.async.cg.shared.global [%0], [%1], 16, %2;"
                 :: "r"(dst), "l"(src), "r"(srcbytes));
}

// ---------------- weight fp32 -> bf16 ---------------------------------------
__global__ void k_cvtw(const float* __restrict__ win, const float* __restrict__ wx,
                       const float* __restrict__ wo) {
    int i = blockIdx.x * 256 + threadIdx.x;
    if (i < NLAYER*2*DIdim*Cch) g_win_bf[i]  = __float2bfloat16(win[i]);
    if (i < NLAYER*48*DIdim)    g_wx_bf[i]   = __float2bfloat16(wx[i]);
    if (i < NLAYER*Cch*DIdim)   g_wout_bf[i] = __float2bfloat16(wo[i]);
}

// ---------------- input transpose (b,c,l) -> (b,l,c) -------------------------
__global__ void k_transpose_in(const float* __restrict__ x) {
    __shared__ float tile[32][33];
    int b = blockIdx.z, c0 = blockIdx.y * 32, l0 = blockIdx.x * 32;
    int tx = threadIdx.x, ty = threadIdx.y;
    #pragma unroll
    for (int i = ty; i < 32; i += 8)
        tile[i][tx] = x[(size_t)(b*Cch + c0 + i)*Lseq + l0 + tx];
    __syncthreads();
    #pragma unroll
    for (int i = ty; i < 32; i += 8)
        g_xs[(size_t)(b*Lseq + l0 + i)*Cch + c0 + tx] = tile[tx][i];
}

// ---------------- layernorm: warp per token, 8 tokens/block ------------------
__global__ void k_ln(const float* __restrict__ w, const float* __restrict__ bias) {
    int warp = threadIdx.x >> 5, lane = threadIdx.x & 31;
    int m = blockIdx.x * 8 + warp;
    const float* row = g_xs + (size_t)m*Cch;
    float v[8], s = 0.f, s2 = 0.f;
    #pragma unroll
    for (int j = 0; j < 8; j++) {
        v[j] = row[lane + 32*j];
        s += v[j]; s2 += v[j]*v[j];
    }
    #pragma unroll
    for (int o = 16; o > 0; o >>= 1) {
        s  += __shfl_xor_sync(0xffffffffu, s, o);
        s2 += __shfl_xor_sync(0xffffffffu, s2, o);
    }
    float mu = s * (1.f/256.f);
    float r  = rsqrtf(s2 * (1.f/256.f) - mu*mu + 1e-5f);
    #pragma unroll
    for (int j = 0; j < 8; j++) {
        int c = lane + 32*j;
        g_xn_bf[(size_t)m*Cch + c] = __float2bfloat16((v[j] - mu)*r*w[c] + bias[c]);
    }
}

// ---------------- bf16 tensor GEMM: C[M,N] (+)= A[M,K] @ W[N,K]^T ------------
// BM=128, BN=64, BK=32, 256 threads = 8 warps (4 M x 2 N), warp tile 32x32.
// 3-stage cp.async, one barrier per chunk; ldmatrix.x4; GP=20 pad; occ 3.
#define GP 20
#define STG 3
#define TILEA (128*GP)
#define TILEB (64*GP)
#define GEMM_SMEM (STG*(TILEA+TILEB)*4)
template<bool ACC, bool BF16OUT>
__launch_bounds__(256, 3)
__global__ void k_gemm_bf(const __nv_bfloat16* __restrict__ A,
                          const __nv_bfloat16* __restrict__ W,
                          void* __restrict__ CoutV, int N, int Kd)
{
    extern __shared__ __align__(16) unsigned smbuf[];
    unsigned* As = smbuf;                 // STG A tiles
    unsigned* Bs = smbuf + STG*TILEA;     // STG B tiles
    const int m0 = blockIdx.y * 128, n0 = blockIdx.x * 64;
    const int tid  = threadIdx.x;
    const int warp = tid >> 5, lane = tid & 31;
    const int wm = (warp & 3) * 32;
    const int wn = (warp >> 2) * 32;
    const int grp = lane >> 2, tig = lane & 3;
    const int l15 = lane & 15, lhi = (lane >> 4) * 4;

    float acc[2][4][4];
    #pragma unroll
    for (int mt = 0; mt < 2; mt++)
        #pragma unroll
        for (int nt = 0; nt < 4; nt++)
            #pragma unroll
            for (int q = 0; q < 4; q++) acc[mt][nt][q] = 0.f;

    const int NC = Kd >> 5;

    auto preload = [&](int c) {
        unsigned* Ab = As + (c % STG) * TILEA;
        unsigned* Bb = Bs + (c % STG) * TILEB;
        #pragma unroll
        for (int i = 0; i < 2; i++) {
            int id = tid + i*256;
            int rr = id >> 2, qq = id & 3;
            cpasync16(smaddr(Ab + rr*GP + qq*4),
                      A + (size_t)(m0 + rr)*Kd + c*32 + qq*8, 16);
        }
        {
            int rr = tid >> 2, qq = tid & 3;      // 64 rows x 4 quads
            int valid = (n0 + rr < N);
            cpasync16(smaddr(Bb + rr*GP + qq*4),
                      W + (size_t)(valid ? (n0 + rr) : 0)*Kd + c*32 + qq*8,
                      valid ? 16 : 0);
        }
        asm volatile("cp.async.commit_group;");
    };

    preload(0);
    if (NC > 1) preload(1);
    for (int c = 0; c < NC; c++) {
        if (c + 1 < NC) { asm volatile("cp.async.wait_group 1;"); }
        else            { asm volatile("cp.async.wait_group 0;"); }
        __syncthreads();
        if (c + 2 < NC) preload(c + 2);
        const unsigned* Ab = As + (c % STG) * TILEA;
        const unsigned* Bb = Bs + (c % STG) * TILEB;
        #pragma unroll
        for (int ks = 0; ks < 2; ks++) {
            int kc = ks * 8;
            unsigned af[2][4], bf[4][2];
            #pragma unroll
            for (int mt = 0; mt < 2; mt++)
                ldsm4(af[mt][0], af[mt][1], af[mt][2], af[mt][3],
                      smaddr(Ab + (wm + mt*16 + l15)*GP + kc + lhi));
            #pragma unroll
            for (int pr = 0; pr < 2; pr++)
                ldsm4(bf[2*pr][0], bf[2*pr+1][0], bf[2*pr][1], bf[2*pr+1][1],
                      smaddr(Bb + (wn + pr*16 + l15)*GP + kc + lhi));
            #pragma unroll
            for (int mt = 0; mt < 2; mt++)
                #pragma unroll
                for (int nt = 0; nt < 4; nt++)
                    mma_bf16(acc[mt][nt], af[mt], bf[nt]);
        }
    }

    // epilogue: c0,c1 -> (grp, 2tig); c2,c3 -> (grp+8, 2tig)
    #pragma unroll
    for (int mt = 0; mt < 2; mt++) {
        #pragma unroll
        for (int nt = 0; nt < 4; nt++) {
            int m = m0 + wm + mt*16 + grp;
            int n = n0 + wn + nt*8 + 2*tig;
            if (n < N) {
                if (BF16OUT) {
                    __nv_bfloat16* Cb = (__nv_bfloat16*)CoutV;
                    *(__nv_bfloat162*)(Cb + (size_t)m*N + n) =
                        __floats2bfloat162_rn(acc[mt][nt][0], acc[mt][nt][1]);
                    *(__nv_bfloat162*)(Cb + (size_t)(m+8)*N + n) =
                        __floats2bfloat162_rn(acc[mt][nt][2], acc[mt][nt][3]);
                } else {
                    float* Cf = (float*)CoutV;
                    float2* p0 = (float2*)(Cf + (size_t)m*N + n);
                    float2* p1 = (float2*)(Cf + (size_t)(m+8)*N + n);
                    if (ACC) {
                        float2 v0 = *p0, v1 = *p1;
                        v0.x += acc[mt][nt][0]; v0.y += acc[mt][nt][1];
                        v1.x += acc[mt][nt][2]; v1.y += acc[mt][nt][3];
                        *p0 = v0; *p1 = v1;
                    } else {
                        *p0 = make_float2(acc[mt][nt][0], acc[mt][nt][1]);
                        *p1 = make_float2(acc[mt][nt][2], acc[mt][nt][3]);
                    }
                }
            }
        }
    }
}

// ---------------- depthwise causal conv (K=4) + silu, 4 tok x 2 ch / thread --
__global__ void k_conv(const float* __restrict__ w, const float* __restrict__ bias) {
    int idx = blockIdx.x * 256 + threadIdx.x;      // over Mtok*DIdim/8
    int d = (idx & 255) * 2;                        // even channel of the pair
    int mg = idx >> 8;                              // token group of 4
    int m0 = mg * 4;
    int l0 = m0 & (Lseq - 1);
    float lo[7], hi[7];
    #pragma unroll
    for (int k = 0; k < 7; k++) {
        int l = l0 - 3 + k;
        if (l >= 0) {
            __nv_bfloat162 v =
                *(const __nv_bfloat162*)&g_xz_bf[(size_t)(m0 - 3 + k)*(2*DIdim) + d];
            lo[k] = __bfloat162float(v.x); hi[k] = __bfloat162float(v.y);
        } else { lo[k] = 0.f; hi[k] = 0.f; }
    }
    float wa0 = w[d*4+0], wa1 = w[d*4+1], wa2 = w[d*4+2], wa3 = w[d*4+3];
    float wb0 = w[d*4+4], wb1 = w[d*4+5], wb2 = w[d*4+6], wb3 = w[d*4+7];
    float ba = bias[d], bb = bias[d+1];
    #pragma unroll
    for (int j = 0; j < 4; j++) {
        float s0 = ba + wa0*lo[j] + wa1*lo[j+1] + wa2*lo[j+2] + wa3*lo[j+3];
        float s1 = bb + wb0*hi[j] + wb1*hi[j+1] + wb2*hi[j+2] + wb3*hi[j+3];
        *(__nv_bfloat162*)&g_xc_bf[(size_t)(m0 + j)*DIdim + d] =
            __floats2bfloat162_rn(siluf(s0), siluf(s1));
    }
}

// ---------------- selective scan (dt fused, z prefetched, gated) -------------
// R10-proven structure: deferred reduction through padded s_p[16][17]
// (conflict-free), NO shuffles in the serial loop.
__launch_bounds__(256)
__global__ void k_scan2(const float* __restrict__ alog, const float* __restrict__ Dp,
                        const float* __restrict__ dw, const float* __restrict__ db) {
    __shared__ __align__(16) float s_dt[32][16], s_x[32][16], s_B[32][16], s_C[32][16];
    __shared__ __align__(16) float s_z[32][16];
    __shared__ __align__(16) float s_P[32][16];
    __shared__ __align__(16) float s_p[32][16][17];
    __shared__ float s_dw[16][17];
    __shared__ float s_db[16], s_D[16];
    int b  = blockIdx.x >> 5;
    int d0 = (blockIdx.x & 31) << 4;
    int tid = threadIdx.x;
    int n  = tid & 15, dg = tid >> 4;
    int d  = d0 + dg;
    float Ad = -__expf(alog[d*DSdim + n]);
    if (tid < 16) { s_D[tid] = Dp[d0 + tid]; s_db[tid] = db[d0 + tid]; }
    s_dw[tid >> 4][tid & 15] = dw[(d0 + (tid >> 4))*16 + (tid & 15)];
    float h = 0.f;
    float rP[2], rx[2], rB[2], rC[2], rZ[2];

    auto ldc = [&](int l0) {
        #pragma unroll
        for (int it = 0; it < 2; it++) {
            int i = tid + it*256;
            int l = i >> 4, j = i & 15;
            size_t t = (size_t)(b*Lseq + l0 + l);
            rP[it] = g_proj[t*48 + j];
            rx[it] = __bfloat162float(g_xc_bf[t*DIdim + d0 + j]);
            rB[it] = g_proj[t*48 + 16 + j];
            rC[it] = g_proj[t*48 + 32 + j];
            rZ[it] = __bfloat162float(g_xz_bf[t*(2*DIdim) + DIdim + d0 + j]);
        }
    };
    auto stc = [&]() {
        #pragma unroll
        for (int it = 0; it < 2; it++) {
            int i = tid + it*256;
            int l = i >> 4, j = i & 15;
            s_P[l][j] = rP[it]; s_x[l][j] = rx[it];
            s_B[l][j] = rB[it]; s_C[l][j] = rC[it];
            s_z[l][j] = rZ[it];
        }
    };
    auto dtcalc = [&]() {
        #pragma unroll
        for (int it = 0; it < 2; it++) {
            int i = tid + it*256;
            int l = i >> 4, j = i & 15;
            float s = s_db[j];
            #pragma unroll
            for (int r = 0; r < 16; r++) s += s_P[l][r] * s_dw[j][r];
            s_dt[l][j] = (s > 15.f) ? s : __logf(1.f + __expf(s));
        }
    };

    ldc(0); stc(); __syncthreads(); dtcalc(); __syncthreads();
    for (int ch = 0; ch < 32; ch++) {
        int l0 = ch * 32;
        if (ch < 31) ldc(l0 + 32);
        #pragma unroll 8
        for (int l = 0; l < 32; l++) {
            float dtv = s_dt[l][dg];
            float w = __expf(dtv * Ad);
            float u = (dtv * s_x[l][dg]) * s_B[l][n];
            h = h * w + u;
            s_p[l][dg][n] = h * s_C[l][n];
        }
        __syncthreads();
        #pragma unroll
        for (int it = 0; it < 2; it++) {
            int i = tid + it*256;
            int l = i >> 4, g = i & 15;
            const float* pr = &s_p[l][g][0];
            float s = 0.f;
            #pragma unroll
            for (int k = 0; k < 16; k++) s += pr[k];
            size_t t = (size_t)(b*Lseq + l0 + l);
            float yv = s + s_x[l][g] * s_D[g];
            float z = s_z[l][g];
            yv *= z / (1.f + __expf(-z));
            g_y_bf[t*DIdim + d0 + g] = __float2bfloat16(yv);
        }
        __syncthreads();
        if (ch < 31) { stc(); __syncthreads(); dtcalc(); __syncthreads(); }
    }
}

// ---------------- SE pool (direct, also zeros BN sums) -----------------------
__global__ void k_pool2() {            // grid Bsz, block 1024
    int b = blockIdx.x, t = threadIdx.x;
    int c = t & 255, q = t >> 8;
    float s = 0.f;
    for (int l = q*256; l < q*256 + 256; l++)
        s += g_xs[(size_t)(b*Lseq + l)*Cch + c];
    __shared__ float sm[4][256];
    sm[q][c] = s;
    __syncthreads();
    if (q == 0)
        g_g0[b*Cch + c] = (sm[0][c] + sm[1][c] + sm[2][c] + sm[3][c]) * (1.f/1024.f);
    if (b == 0 && t < 512) g_stats[t] = 0.f;
}
__global__ void k_se(const float* __restrict__ w1, const float* __restrict__ b1,
                     const float* __restrict__ w2, const float* __restrict__ b2) {
    __shared__ float sg[Bsz*Cch];
    __shared__ float sh[Bsz*64];
    int t = threadIdx.x;
    for (int i = t; i < Bsz*Cch; i += 256) sg[i] = g_g0[i];
    __syncthreads();
    for (int i = t; i < Bsz*64; i += 256) {
        int b = i >> 6, j = i & 63;
        float s = b1[j];
        const float* wr = w1 + j*256;
        const float* gr = sg + b*256;
        #pragma unroll 8
        for (int c = 0; c < 256; c++) s += gr[c] * wr[c];
        sh[i] = fmaxf(s, 0.f);
    }
    __syncthreads();
    for (int i = t; i < Bsz*Cch; i += 256) {
        int b = i >> 8, c = i & 255;
        float s = b2[c];
        const float* wr = w2 + c*64;
        const float* hr = sh + b*64;
        #pragma unroll 8
        for (int j = 0; j < 64; j++) s += hr[j] * wr[j];
        g_gate[i] = 1.f / (1.f + __expf(-s));
    }
}

// ---------------- y = xo*g + residual (b,c,l) + fused BN partial sums --------
__global__ void k_ybn(const float* __restrict__ x) {
    __shared__ float tile[32][33];
    int b = blockIdx.z, c0 = blockIdx.y * 32, l0 = blockIdx.x * 32;
    int tx = threadIdx.x, ty = threadIdx.y;
    #pragma unroll
    for (int i = ty; i < 32; i += 8)
        tile[i][tx] = g_xs[(size_t)(b*Lseq + l0 + i)*Cch + c0 + tx];   // tile[l][c]
    __syncthreads();
    #pragma unroll
    for (int i = ty; i < 32; i += 8) {
        int c = c0 + i;
        size_t o = (size_t)(b*Cch + c)*Lseq + l0 + tx;
        float v = tile[tx][i] * g_gate[b*Cch + c] + x[o];
        g_ybn[o] = v;
        float s = v, s2 = v*v;
        #pragma unroll
        for (int w = 16; w > 0; w >>= 1) {
            s  += __shfl_xor_sync(0xffffffffu, s, w);
            s2 += __shfl_xor_sync(0xffffffffu, s2, w);
        }
        if (tx == 0) {
            atomicAdd(&g_stats[c], s);
            atomicAdd(&g_stats[Cch + c], s2);
        }
    }
}

// ---------------- batchnorm apply (float4, stats from raw sums) --------------
__global__ void k_bnapply(float* __restrict__ out, const float* __restrict__ bw,
                          const float* __restrict__ bb) {
    int idx = blockIdx.x * 256 + threadIdx.x;   // over Bsz*Cch*Lseq/4
    int c = (idx >> 8) & 255;                   // 256 float4 per (b,c) row
    float mu  = g_stats[c] * (1.f/8192.f);
    float rs  = rsqrtf(g_stats[Cch + c] * (1.f/8192.f) - mu*mu + 1e-5f);
    float wc  = rs * bw[c], bc = bb[c];
    float4 v = *(const float4*)&g_ybn[(size_t)idx*4];
    v.x = (v.x - mu) * wc + bc;
    v.y = (v.y - mu) * wc + bc;
    v.z = (v.z - mu) * wc + bc;
    v.w = (v.w - mu) * wc + bc;
    *(float4*)&out[(size_t)idx*4] = v;
}

// ---------------- host driver ------------------------------------------------
extern "C" void kernel_launch(void* const* d_in, const int* in_sizes, int n_in,
                              void* d_out, int out_size)
{
    const float* x         = (const float*)d_in[0];
    const float* ln_w      = (const float*)d_in[1];
    const float* ln_b      = (const float*)d_in[2];
    const float* in_proj_w = (const float*)d_in[3];
    const float* conv_w    = (const float*)d_in[4];
    const float* conv_b    = (const float*)d_in[5];
    const float* x_proj_w  = (const float*)d_in[6];
    const float* dt_proj_w = (const float*)d_in[7];
    const float* dt_proj_b = (const float*)d_in[8];
    const float* A_log     = (const float*)d_in[9];
    const float* Dp        = (const float*)d_in[10];
    const float* out_proj_w= (const float*)d_in[11];
    const float* se_w1     = (const float*)d_in[12];
    const float* se_b1     = (const float*)d_in[13];
    const float* se_w2     = (const float*)d_in[14];
    const float* se_b2     = (const float*)d_in[15];
    const float* bn_w      = (const float*)d_in[16];
    const float* bn_b      = (const float*)d_in[17];
    float* out = (float*)d_out;

    void *p;
    cudaGetSymbolAddress(&p, g_xn_bf);   __nv_bfloat16* pxn  = (__nv_bfloat16*)p;
    cudaGetSymbolAddress(&p, g_xz_bf);   __nv_bfloat16* pxzb = (__nv_bfloat16*)p;
    cudaGetSymbolAddress(&p, g_xc_bf);   __nv_bfloat16* pxcb = (__nv_bfloat16*)p;
    cudaGetSymbolAddress(&p, g_proj);    float* pproj = (float*)p;
    cudaGetSymbolAddress(&p, g_y_bf);    __nv_bfloat16* pyb  = (__nv_bfloat16*)p;
    cudaGetSymbolAddress(&p, g_xs);      float* pxs  = (float*)p;
    cudaGetSymbolAddress(&p, g_win_bf);  __nv_bfloat16* pwin = (__nv_bfloat16*)p;
    cudaGetSymbolAddress(&p, g_wx_bf);   __nv_bfloat16* pwx  = (__nv_bfloat16*)p;
    cudaGetSymbolAddress(&p, g_wout_bf); __nv_bfloat16* pwo  = (__nv_bfloat16*)p;

    cudaFuncSetAttribute(k_gemm_bf<false, true>,
                         cudaFuncAttributeMaxDynamicSharedMemorySize, GEMM_SMEM);
    cudaFuncSetAttribute(k_gemm_bf<false, false>,
                         cudaFuncAttributeMaxDynamicSharedMemorySize, GEMM_SMEM);
    cudaFuncSetAttribute(k_gemm_bf<true, false>,
                         cudaFuncAttributeMaxDynamicSharedMemorySize, GEMM_SMEM);

    k_cvtw<<<(NLAYER*2*DIdim*Cch + 255)/256, 256>>>(in_proj_w, x_proj_w, out_proj_w);
    dim3 tb(32, 8);
    k_transpose_in<<<dim3(32, 8, Bsz), tb>>>(x);

    for (int i = 0; i < NLAYER; i++) {
        k_ln<<<Mtok/8, 256>>>(ln_w + i*Cch, ln_b + i*Cch);
        k_gemm_bf<false, true><<<dim3(16, 64), 256, GEMM_SMEM>>>(
            pxn, pwin + (size_t)i*2*DIdim*Cch, pxzb, 2*DIdim, Cch);
        k_conv<<<Mtok*DIdim/2048, 256>>>(conv_w + i*DIdim*4, conv_b + i*DIdim);
        k_gemm_bf<false, false><<<dim3(1, 64), 256, GEMM_SMEM>>>(
            pxcb, pwx + (size_t)i*48*DIdim, pproj, 48, DIdim);
        k_scan2<<<256, 256>>>(A_log + i*DIdim*DSdim, Dp + i*DIdim,
                              dt_proj_w + i*DIdim*16, dt_proj_b + i*DIdim);
        k_gemm_bf<true, false><<<dim3(4, 64), 256, GEMM_SMEM>>>(
            pyb, pwo + (size_t)i*Cch*DIdim, pxs, Cch, DIdim);
    }

    k_pool2<<<Bsz, 1024>>>();
    k_se<<<1, 256>>>(se_w1, se_b1, se_w2, se_b2);
    k_ybn<<<dim3(32, 8, Bsz), tb>>>(x);
    k_bnapply<<<Bsz*Cch*Lseq/1024, 256>>>(out, bn_w, bn_b);

    (void)in_sizes; (void)n_in; (void)out_size;
}